// round 2
// baseline (speedup 1.0000x reference)
#include <cuda_runtime.h>
#include <math.h>

#define K_CODES 1024
#define D 64
#define ROWP 68                 // padded smem row (floats): 272B, 16B-aligned, 2-way-max bank groups
#define SMEM_BYTES ((64 * ROWP + 128 * ROWP + 64) * 4 + 64 * 4)

__device__ unsigned int g_counts[K_CODES];
__device__ float g_esq[K_CODES];
__device__ double g_sumsq;

// packed dual-fp32 FMA (Blackwell f32x2 path; ptxas never emits this from C++)
__device__ __forceinline__ void fma2(unsigned long long& d_, unsigned long long a,
                                     unsigned long long b) {
    asm("fma.rn.f32x2 %0, %1, %2, %0;" : "+l"(d_) : "l"(a), "l"(b));
}

// ---------------------------------------------------------------------------
// Kernel 1: zero scratch, precompute ||e_k||^2
// ---------------------------------------------------------------------------
__global__ void vq_init(const float* __restrict__ cb) {
    int k = blockIdx.x * blockDim.x + threadIdx.x;
    if (k < K_CODES) {
        g_counts[k] = 0u;
        float s = 0.f;
#pragma unroll 8
        for (int d = 0; d < D; ++d) {
            float v = cb[k * D + d];
            s = fmaf(v, v, s);
        }
        g_esq[k] = s;
        if (k == 0) g_sumsq = 0.0;
    }
}

// ---------------------------------------------------------------------------
// Kernel 2: distances + argmin + gather + histogram + sum of squared diff
//   CTA: 64 tokens x (8 chunks of 128 codes). 256 threads as 16x16.
//   Thread micro-tile: 4 tokens x 8 codes, f32x2 accumulators paired over D.
// ---------------------------------------------------------------------------
__global__ __launch_bounds__(256, 1) void vq_main(const float* __restrict__ z,
                                                  const float* __restrict__ cb,
                                                  float* __restrict__ out, int N) {
    extern __shared__ float sm[];
    float* zs  = sm;                                // [64][ROWP]
    float* cs  = sm + 64 * ROWP;                    // [128][ROWP]
    float* zsq = sm + 64 * ROWP + 128 * ROWP;       // [64]
    int*   widx = (int*)(zsq + 64);                 // [64]

    const int tid = threadIdx.x;
    const int tx = tid & 15, ty = tid >> 4;
    const int tok0 = blockIdx.x * 64;

    // stage z tile (tokens x D), padded rows
    for (int i = tid; i < 64 * 16; i += 256) {
        int r = i >> 4, c = i & 15;
        *reinterpret_cast<float4*>(&zs[r * ROWP + c * 4]) =
            *reinterpret_cast<const float4*>(&z[(size_t)(tok0 + r) * D + c * 4]);
    }
    __syncthreads();
    if (tid < 64) {
        float s = 0.f;
        for (int d = 0; d < D; ++d) {
            float v = zs[tid * ROWP + d];
            s = fmaf(v, v, s);
        }
        zsq[tid] = s;
    }
    __syncthreads();

    float zq[4];
#pragma unroll
    for (int i = 0; i < 4; ++i) zq[i] = zsq[ty * 4 + i];

    float best[4];
    int bidx[4];
#pragma unroll
    for (int i = 0; i < 4; ++i) { best[i] = 3.4e38f; bidx[i] = 0; }

    for (int ch = 0; ch < 8; ++ch) {
        __syncthreads();  // guard cs reuse
        for (int i = tid; i < 128 * 16; i += 256) {
            int r = i >> 4, c = i & 15;
            *reinterpret_cast<float4*>(&cs[r * ROWP + c * 4]) =
                *reinterpret_cast<const float4*>(&cb[(size_t)(ch * 128 + r) * D + c * 4]);
        }
        __syncthreads();

        unsigned long long acc[4][8];
#pragma unroll
        for (int i = 0; i < 4; ++i)
#pragma unroll
            for (int j = 0; j < 8; ++j) acc[i][j] = 0ull;

#pragma unroll
        for (int d4 = 0; d4 < 16; ++d4) {
            ulonglong2 a[4], b[8];
#pragma unroll
            for (int i = 0; i < 4; ++i)
                a[i] = *reinterpret_cast<const ulonglong2*>(
                    &zs[(ty * 4 + i) * ROWP + d4 * 4]);
#pragma unroll
            for (int j = 0; j < 8; ++j)
                b[j] = *reinterpret_cast<const ulonglong2*>(
                    &cs[(tx + 16 * j) * ROWP + d4 * 4]);
#pragma unroll
            for (int i = 0; i < 4; ++i)
#pragma unroll
                for (int j = 0; j < 8; ++j) {
                    fma2(acc[i][j], a[i].x, b[j].x);  // even-d partials
                    fma2(acc[i][j], a[i].y, b[j].y);  // odd-d partials
                }
        }

        // scores: exact reference formula (z_sq - 2*dot) + e_sq in fp32.
        // j ascending => code index ascending => strict '<' keeps first min.
#pragma unroll
        for (int j = 0; j < 8; ++j) {
            int cg = ch * 128 + tx + 16 * j;
            float esq = g_esq[cg];
#pragma unroll
            for (int i = 0; i < 4; ++i) {
                float2 p = *reinterpret_cast<float2*>(&acc[i][j]);
                float dot = p.x + p.y;
                float s = (zq[i] - 2.0f * dot) + esq;
                if (s < best[i]) { best[i] = s; bidx[i] = cg; }
            }
        }
    }

    // cross-thread argmin reduce (overlay scratch on cs region)
    __syncthreads();
    float* rv = cs;                     // [64][16]
    int* ri = (int*)(cs + 64 * 16);     // [64][16]
#pragma unroll
    for (int i = 0; i < 4; ++i) {
        int t = ty * 4 + i;
        rv[t * 16 + tx] = best[i];
        ri[t * 16 + tx] = bidx[i];
    }
    __syncthreads();
    if (tid < 64) {
        float bv = rv[tid * 16];
        int bi = ri[tid * 16];
        for (int x = 1; x < 16; ++x) {
            float v = rv[tid * 16 + x];
            int ix = ri[tid * 16 + x];
            if (v < bv || (v == bv && ix < bi)) { bv = v; bi = ix; }
        }
        widx[tid] = bi;
        out[(size_t)N * D + tok0 + tid] = (float)bi;         // indices section
        atomicAdd(&g_counts[bi], 1u);
    }
    __syncthreads();

    // gather z_q, write output rows, accumulate sum((z_q - z_e)^2)
    int t = tid >> 2, seg = tid & 3;
    int bi = widx[t];
    float part = 0.f;
#pragma unroll
    for (int c4 = 0; c4 < 4; ++c4) {
        int d = seg * 16 + c4 * 4;
        float4 cv = *reinterpret_cast<const float4*>(&cb[(size_t)bi * D + d]);
        *reinterpret_cast<float4*>(&out[(size_t)(tok0 + t) * D + d]) = cv;
        float4 zv = *reinterpret_cast<const float4*>(&zs[t * ROWP + d]);
        float dx = cv.x - zv.x, dy = cv.y - zv.y;
        float dz = cv.z - zv.z, dw = cv.w - zv.w;
        part += dx * dx + dy * dy + dz * dz + dw * dw;
    }
#pragma unroll
    for (int off = 16; off > 0; off >>= 1)
        part += __shfl_down_sync(0xffffffffu, part, off);
    __shared__ float bsum;
    if (tid == 0) bsum = 0.f;
    __syncthreads();
    if ((tid & 31) == 0) atomicAdd(&bsum, part);
    __syncthreads();
    if (tid == 0) atomicAdd(&g_sumsq, (double)bsum);
}

// ---------------------------------------------------------------------------
// Kernel 3: entropy / perplexity / losses
// ---------------------------------------------------------------------------
__global__ void vq_finalize(float* __restrict__ out, int N) {
    __shared__ double red[1024];
    int k = threadIdx.x;
    float cnt = (float)g_counts[k];
    float avg = cnt / (float)N + 1e-10f;   // mimic fp32 avg_probs
    double p = (double)avg;
    red[k] = -p * log(p);
    __syncthreads();
    for (int s = 512; s > 0; s >>= 1) {
        if (k < s) red[k] += red[k + s];
        __syncthreads();
    }
    if (k == 0) {
        double H = red[0];
        double mean = g_sumsq / ((double)N * D);
        size_t base = (size_t)N * D + N;
        out[base + 0] = (float)mean;                           // codebook_loss
        out[base + 1] = (float)(0.25 * mean);                  // commitment_loss
        out[base + 2] = (float)(-0.1 * (H / log(1024.0)));     // entropy_loss
        out[base + 3] = (float)exp(H);                         // perplexity
    }
}

// ---------------------------------------------------------------------------
extern "C" void kernel_launch(void* const* d_in, const int* in_sizes, int n_in,
                              void* d_out, int out_size) {
    const float* z = (const float*)d_in[0];
    const float* cb = (const float*)d_in[1];
    float* out = (float*)d_out;
    int N = in_sizes[0] / D;

    cudaFuncSetAttribute(vq_main, cudaFuncAttributeMaxDynamicSharedMemorySize,
                         SMEM_BYTES);

    vq_init<<<(K_CODES + 255) / 256, 256>>>(cb);
    vq_main<<<N / 64, 256, SMEM_BYTES>>>(z, cb, out, N);
    vq_finalize<<<1, 1024>>>(out, N);
}

// round 4
// speedup vs baseline: 1.1294x; 1.1294x over previous
#include <cuda_runtime.h>
#include <cuda_bf16.h>
#include <math.h>
#include <stdint.h>

#define K_CODES 1024
#define D 64
#define NTOK 131072
#define WIN 2e-5f
#define BIGF 3.4e38f

// dynamic smem layout (bytes)
#define OFF_ZSQ 0
#define OFF_ESQ 512
#define OFF_B0  8192
#define OFF_B1  40960
#define SMEM_SZ 73728

__device__ unsigned int g_counts[K_CODES];
__device__ float g_esq[K_CODES];
__device__ double g_sumsq;
__device__ __align__(16) __nv_bfloat16 g_eh[K_CODES * D];
__device__ __align__(16) __nv_bfloat16 g_el[K_CODES * D];
__device__ float g_zsq[NTOK];
__device__ unsigned char g_ovf[NTOK];
__device__ __align__(8) short g_cand[NTOK * 16];

// ---------------- helpers ----------------
__device__ __forceinline__ uint32_t smem_u32(const void* p) {
    uint32_t a;
    asm("{ .reg .u64 t; cvta.to.shared.u64 t, %1; cvt.u32.u64 %0, t; }" : "=r"(a) : "l"(p));
    return a;
}
__device__ __forceinline__ void ldsm4(uint32_t* r, uint32_t addr) {
    asm volatile("ldmatrix.sync.aligned.m8n8.x4.shared.b16 {%0,%1,%2,%3}, [%4];"
                 : "=r"(r[0]), "=r"(r[1]), "=r"(r[2]), "=r"(r[3]) : "r"(addr));
}
__device__ __forceinline__ void mma16816(float* c, const uint32_t* a, uint32_t b0, uint32_t b1) {
    asm volatile(
        "mma.sync.aligned.m16n8k16.row.col.f32.bf16.bf16.f32 "
        "{%0,%1,%2,%3}, {%4,%5,%6,%7}, {%8,%9}, {%0,%1,%2,%3};"
        : "+f"(c[0]), "+f"(c[1]), "+f"(c[2]), "+f"(c[3])
        : "r"(a[0]), "r"(a[1]), "r"(a[2]), "r"(a[3]), "r"(b0), "r"(b1));
}
// sorted keep-4 insert (guarded; body runs rarely)
__device__ __forceinline__ void ins4(float& e0, float& e1, float& e2, float& e3,
                                     int& i0, int& i1, int& i2, int& i3,
                                     float s, int id) {
    if (s < e3) {
        bool c0 = s < e0, c1 = s < e1, c2 = s < e2;
        float n3 = c2 ? e2 : s;              int m3 = c2 ? i2 : id;
        float n2 = c1 ? e1 : (c2 ? s : e2);  int m2 = c1 ? i1 : (c2 ? id : i2);
        float n1 = c0 ? e0 : (c1 ? s : e1);  int m1 = c0 ? i0 : (c1 ? id : i1);
        e0 = c0 ? s : e0;                    i0 = c0 ? id : i0;
        e1 = n1; i1 = m1; e2 = n2; i2 = m2; e3 = n3; i3 = m3;
    }
}
// exact score with R1's accumulation order (even/odd fmaf chains)
__device__ __forceinline__ float exact_score(const float* zr, const float* er,
                                             float zsq, float esq) {
    float aE = 0.f, aO = 0.f;
#pragma unroll
    for (int i = 0; i < 16; ++i) {
        float4 v = ((const float4*)zr)[i];
        float4 c = ((const float4*)er)[i];
        aE = fmaf(v.x, c.x, aE); aE = fmaf(v.z, c.z, aE);
        aO = fmaf(v.y, c.y, aO); aO = fmaf(v.w, c.w, aO);
    }
    float dot = aE + aO;
    return (zsq - 2.0f * dot) + esq;
}

// ---------------------------------------------------------------------------
// Kernel 0: zero scratch + esq + bf16 splits of codebook
// ---------------------------------------------------------------------------
__global__ void vq_prep(const float* __restrict__ cb) {
    int k = blockIdx.x * blockDim.x + threadIdx.x;
    if (k >= K_CODES) return;
    g_counts[k] = 0u;
    if (k == 0) g_sumsq = 0.0;
    float s = 0.f;
    for (int d = 0; d < D; ++d) {
        float v = cb[k * D + d];
        s = fmaf(v, v, s);
        __nv_bfloat16 h = __float2bfloat16(v);
        g_eh[k * D + d] = h;
        g_el[k * D + d] = __float2bfloat16(v - __bfloat162float(h));
    }
    g_esq[k] = s;
}

// ---------------------------------------------------------------------------
// stage a 128-code chunk of (eh, el) into smem with 16B-block XOR swizzle
// ---------------------------------------------------------------------------
__device__ __forceinline__ void stage_chunk(char* dst, int ch, int tid) {
    const uint4* sh = (const uint4*)((const char*)g_eh + (size_t)ch * 16384);
    const uint4* sl = (const uint4*)((const char*)g_el + (size_t)ch * 16384);
#pragma unroll
    for (int it = 0; it < 4; ++it) {
        int b = it * 256 + tid;           // 1024 16B blocks
        int row = b >> 3, blk = b & 7;
        int off = row * 128 + ((blk ^ (row & 7)) << 4);
        *(uint4*)(dst + off) = sh[b];
        *(uint4*)(dst + 16384 + off) = sl[b];
    }
}

// ---------------------------------------------------------------------------
// Kernel A: HMMA bf16-split distance scan -> per-token candidate sets
//   CTA: 128 tokens, 256 thr (8 warps x 16 tokens); codes in 8 chunks of 128.
// ---------------------------------------------------------------------------
__global__ __launch_bounds__(256) void vq_mma(const float* __restrict__ z) {
    extern __shared__ __align__(1024) char smb[];
    const uint32_t sb = smem_u32(smb);
    float* zsq_s = (float*)(smb + OFF_ZSQ);
    float* esq_s = (float*)(smb + OFF_ESQ);
    const int tid = threadIdx.x;
    const int w = tid >> 5, l = tid & 31;
    const int tok0 = blockIdx.x * 128;

    if (tid < 128) {   // zsq, sequential d ascending (matches R1)
        const float4* zr = (const float4*)(z + (size_t)(tok0 + tid) * D);
        float s = 0.f;
#pragma unroll
        for (int i = 0; i < 16; ++i) {
            float4 v = zr[i];
            s = fmaf(v.x, v.x, s); s = fmaf(v.y, v.y, s);
            s = fmaf(v.z, v.z, s); s = fmaf(v.w, v.w, s);
        }
        zsq_s[tid] = s;
        g_zsq[tok0 + tid] = s;
    }
    for (int i = tid; i < K_CODES; i += 256) esq_s[i] = g_esq[i];

    // A fragments (zh, zl) straight from gmem
    const int r0 = w * 16 + (l >> 2), r1 = r0 + 8;
    uint32_t ah[4][4], al[4][4];
    {
        const float* zb = z + (size_t)tok0 * D;
#pragma unroll
        for (int ks = 0; ks < 4; ++ks) {
            int c = ks * 16 + (l & 3) * 2;
#pragma unroll
            for (int q = 0; q < 4; ++q) {
                int rr = (q & 1) ? r1 : r0;
                int cc = c + ((q >> 1) ? 8 : 0);
                float2 v = *(const float2*)(zb + (size_t)rr * D + cc);
                __nv_bfloat162 h, lo;
                h.x = __float2bfloat16(v.x); h.y = __float2bfloat16(v.y);
                lo.x = __float2bfloat16(v.x - __bfloat162float(h.x));
                lo.y = __float2bfloat16(v.y - __bfloat162float(h.y));
                ah[ks][q] = *(uint32_t*)&h;
                al[ks][q] = *(uint32_t*)&lo;
            }
        }
    }

    stage_chunk(smb + OFF_B0, 0, tid);
    __syncthreads();
    const float zs0 = zsq_s[w * 16 + (l >> 2)];
    const float zs1 = zsq_s[w * 16 + (l >> 2) + 8];

    float e00 = BIGF, e01 = BIGF, e02 = BIGF, e03 = BIGF;
    float e10 = BIGF, e11 = BIGF, e12 = BIGF, e13 = BIGF;
    int i00 = -1, i01 = -1, i02 = -1, i03 = -1;
    int i10 = -1, i11 = -1, i12 = -1, i13 = -1;

    const int g = l >> 3, ii = l & 7;
    for (int ch = 0; ch < 8; ++ch) {
        const int cur = ch & 1;
        if (ch < 7) stage_chunk(smb + (cur ? OFF_B0 : OFF_B1), ch + 1, tid);
        uint32_t bb = sb + (cur ? OFF_B1 : OFF_B0);
        uint32_t baseLo = bb + ii * 128 + ((g ^ ii) << 4);
        uint32_t baseHi = bb + ii * 128 + (((g + 4) ^ ii) << 4);
#pragma unroll 4
        for (int j = 0; j < 16; ++j) {
            uint32_t eh[8], el[8];
            ldsm4(eh, baseLo + j * 1024);
            ldsm4(eh + 4, baseHi + j * 1024);
            ldsm4(el, baseLo + 16384 + j * 1024);
            ldsm4(el + 4, baseHi + 16384 + j * 1024);
            float acc[4] = {0.f, 0.f, 0.f, 0.f};
#pragma unroll
            for (int ks = 0; ks < 4; ++ks) mma16816(acc, ah[ks], eh[2 * ks], eh[2 * ks + 1]);
#pragma unroll
            for (int ks = 0; ks < 4; ++ks) mma16816(acc, al[ks], eh[2 * ks], eh[2 * ks + 1]);
#pragma unroll
            for (int ks = 0; ks < 4; ++ks) mma16816(acc, ah[ks], el[2 * ks], el[2 * ks + 1]);

            int code0 = ch * 128 + j * 8 + (l & 3) * 2;
            float2 eq = *(const float2*)(esq_s + code0);
            float s00 = (zs0 - 2.f * acc[0]) + eq.x;
            float s01 = (zs0 - 2.f * acc[1]) + eq.y;
            float s10 = (zs1 - 2.f * acc[2]) + eq.x;
            float s11 = (zs1 - 2.f * acc[3]) + eq.y;
            if (fminf(s00, s01) < e00 + WIN) {
                ins4(e00, e01, e02, e03, i00, i01, i02, i03, s00, code0);
                ins4(e00, e01, e02, e03, i00, i01, i02, i03, s01, code0 + 1);
            }
            if (fminf(s10, s11) < e10 + WIN) {
                ins4(e10, e11, e12, e13, i10, i11, i12, i13, s10, code0);
                ins4(e10, e11, e12, e13, i10, i11, i12, i13, s11, code0 + 1);
            }
        }
        __syncthreads();
    }

    // quad (4-lane) reduce: global best + overflow flag; write candidates
    float gb0 = e00, gb1 = e10;
    gb0 = fminf(gb0, __shfl_xor_sync(~0u, gb0, 1));
    gb0 = fminf(gb0, __shfl_xor_sync(~0u, gb0, 2));
    gb1 = fminf(gb1, __shfl_xor_sync(~0u, gb1, 1));
    gb1 = fminf(gb1, __shfl_xor_sync(~0u, gb1, 2));
    int ov0 = (e03 <= gb0 + WIN) ? 1 : 0;
    int ov1 = (e13 <= gb1 + WIN) ? 1 : 0;
    ov0 |= __shfl_xor_sync(~0u, ov0, 1); ov0 |= __shfl_xor_sync(~0u, ov0, 2);
    ov1 |= __shfl_xor_sync(~0u, ov1, 1); ov1 |= __shfl_xor_sync(~0u, ov1, 2);

    const int t0 = tok0 + w * 16 + (l >> 2), t1 = t0 + 8;
    unsigned long long p0 =
        (unsigned long long)(unsigned short)i00 |
        ((unsigned long long)(unsigned short)i01 << 16) |
        ((unsigned long long)(unsigned short)i02 << 32) |
        ((unsigned long long)(unsigned short)i03 << 48);
    unsigned long long p1 =
        (unsigned long long)(unsigned short)i10 |
        ((unsigned long long)(unsigned short)i11 << 16) |
        ((unsigned long long)(unsigned short)i12 << 32) |
        ((unsigned long long)(unsigned short)i13 << 48);
    *(unsigned long long*)(g_cand + (size_t)t0 * 16 + (l & 3) * 4) = p0;
    *(unsigned long long*)(g_cand + (size_t)t1 * 16 + (l & 3) * 4) = p1;
    if ((l & 3) == 0) {
        g_ovf[t0] = (unsigned char)ov0;
        g_ovf[t1] = (unsigned char)ov1;
    }
}

// ---------------------------------------------------------------------------
// Kernel B: exact resolve (one warp per token) + full epilogue
// ---------------------------------------------------------------------------
__global__ __launch_bounds__(256) void vq_resolve(const float* __restrict__ z,
                                                  const float* __restrict__ cb,
                                                  float* __restrict__ out, int N) {
    const int warp = (blockIdx.x * blockDim.x + threadIdx.x) >> 5;
    const int l = threadIdx.x & 31;
    const int nw = (gridDim.x * blockDim.x) >> 5;
    double wsum = 0.0;

    for (int tok = warp; tok < N; tok += nw) {
        const float* zr = z + (size_t)tok * D;
        float zsq = g_zsq[tok];
        int ovf = g_ovf[tok];
        float s = BIGF;
        int bi = 0x7FFFFFFF;
        if (!ovf) {
            int id = -1;
            if (l < 16) id = g_cand[(size_t)tok * 16 + l];
            if (id >= 0) {
                s = exact_score(zr, cb + (size_t)id * D, zsq, g_esq[id]);
                bi = id;
            }
        } else {
            for (int c = l * 32; c < l * 32 + 32; ++c) {
                float sc = exact_score(zr, cb + (size_t)c * D, zsq, g_esq[c]);
                if (sc < s) { s = sc; bi = c; }   // ascending -> lowest idx on tie
            }
        }
        // lexicographic (score, idx) min across warp
#pragma unroll
        for (int o = 16; o > 0; o >>= 1) {
            float s2 = __shfl_xor_sync(~0u, s, o);
            int i2 = __shfl_xor_sync(~0u, bi, o);
            if (s2 < s || (s2 == s && i2 < bi)) { s = s2; bi = i2; }
        }
        if (l == 0) {
            out[(size_t)N * D + tok] = (float)bi;
            atomicAdd(&g_counts[bi], 1u);
        }
        // straight-through z_q write + diff^2
        int d = l * 2;
        float2 cv = *(const float2*)(cb + (size_t)bi * D + d);
        float2 zv = *(const float2*)(zr + d);
        float dx = cv.x - zv.x, dy = cv.y - zv.y;
        *(float2*)(out + (size_t)tok * D + d) = make_float2(zv.x + dx, zv.y + dy);
        float part = dx * dx + dy * dy;
#pragma unroll
        for (int o = 16; o > 0; o >>= 1) part += __shfl_xor_sync(~0u, part, o);
        if (l == 0) wsum += (double)part;
    }
    if (l == 0) atomicAdd(&g_sumsq, wsum);
}

// ---------------------------------------------------------------------------
// Kernel C: entropy / perplexity / losses
// ---------------------------------------------------------------------------
__global__ void vq_finalize(float* __restrict__ out, int N) {
    __shared__ double red[1024];
    int k = threadIdx.x;
    float avg = (float)g_counts[k] / (float)N + 1e-10f;
    double p = (double)avg;
    red[k] = -p * log(p);
    __syncthreads();
    for (int s = 512; s > 0; s >>= 1) {
        if (k < s) red[k] += red[k + s];
        __syncthreads();
    }
    if (k == 0) {
        double H = red[0];
        double mean = g_sumsq / ((double)N * D);
        size_t base = (size_t)N * D + N;
        out[base + 0] = (float)mean;
        out[base + 1] = (float)(0.25 * mean);
        out[base + 2] = (float)(-0.1 * (H / log(1024.0)));
        out[base + 3] = (float)exp(H);
    }
}

// ---------------------------------------------------------------------------
extern "C" void kernel_launch(void* const* d_in, const int* in_sizes, int n_in,
                              void* d_out, int out_size) {
    const float* z = (const float*)d_in[0];
    const float* cb = (const float*)d_in[1];
    float* out = (float*)d_out;
    int N = in_sizes[0] / D;

    cudaFuncSetAttribute(vq_mma, cudaFuncAttributeMaxDynamicSharedMemorySize, SMEM_SZ);

    vq_prep<<<(K_CODES + 255) / 256, 256>>>(cb);
    vq_mma<<<N / 128, 256, SMEM_SZ>>>(z);
    vq_resolve<<<512, 256>>>(z, cb, out, N);
    vq_finalize<<<1, 1024>>>(out, N);
}

// round 5
// speedup vs baseline: 1.4579x; 1.2909x over previous
#include <cuda_runtime.h>
#include <cuda_bf16.h>
#include <math.h>
#include <stdint.h>

#define K_CODES 1024
#define D 64
#define WIN 3e-5f
#define BIGF 3.4e38f

// dynamic smem layout (bytes)
#define OFF_ZSQ  0          // float[128]
#define OFF_ESQ  512        // float[1024]
#define OFF_B0   8192       // chunk buf0: eh 16KB + el 16KB
#define OFF_B1   40960      // chunk buf1
#define OFF_WIDX 73728      // int[128]  (bit31 = ambiguous)
#define OFF_BSUM 74240      // float
#define SMEM_SZ  74304

__device__ unsigned int g_counts[K_CODES];
__device__ float g_esq[K_CODES];
__device__ double g_sumsq;
__device__ __align__(16) __nv_bfloat16 g_eh[K_CODES * D];
__device__ __align__(16) __nv_bfloat16 g_el[K_CODES * D];

// ---------------- helpers ----------------
__device__ __forceinline__ uint32_t smem_u32(const void* p) {
    uint32_t a;
    asm("{ .reg .u64 t; cvta.to.shared.u64 t, %1; cvt.u32.u64 %0, t; }" : "=r"(a) : "l"(p));
    return a;
}
__device__ __forceinline__ void ldsm4(uint32_t* r, uint32_t addr) {
    asm volatile("ldmatrix.sync.aligned.m8n8.x4.shared.b16 {%0,%1,%2,%3}, [%4];"
                 : "=r"(r[0]), "=r"(r[1]), "=r"(r[2]), "=r"(r[3]) : "r"(addr));
}
__device__ __forceinline__ void mma16816(float* c, const uint32_t* a, uint32_t b0, uint32_t b1) {
    asm volatile(
        "mma.sync.aligned.m16n8k16.row.col.f32.bf16.bf16.f32 "
        "{%0,%1,%2,%3}, {%4,%5,%6,%7}, {%8,%9}, {%0,%1,%2,%3};"
        : "+f"(c[0]), "+f"(c[1]), "+f"(c[2]), "+f"(c[3])
        : "r"(a[0]), "r"(a[1]), "r"(a[2]), "r"(a[3]), "r"(b0), "r"(b1));
}
// exact score, R1's accumulation order (even/odd fmaf chains)
__device__ __forceinline__ float exact_score(const float* zr, const float* er,
                                             float zsq, float esq) {
    float aE = 0.f, aO = 0.f;
#pragma unroll
    for (int i = 0; i < 16; ++i) {
        float4 v = ((const float4*)zr)[i];
        float4 c = ((const float4*)er)[i];
        aE = fmaf(v.x, c.x, aE); aE = fmaf(v.z, c.z, aE);
        aO = fmaf(v.y, c.y, aO); aO = fmaf(v.w, c.w, aO);
    }
    return (zsq - 2.0f * (aE + aO)) + esq;
}
// track (b1,i1,b2); codes arrive in ascending idx => strict '<' keeps lowest idx
__device__ __forceinline__ void track(float& b1, int& i1, float& b2, float s, int idx) {
    if (s < b2) {
        if (s < b1) { b2 = b1; b1 = s; i1 = idx; }
        else b2 = s;
    }
}

// ---------------------------------------------------------------------------
// Kernel 0: zero scratch + esq + bf16 splits of codebook
// ---------------------------------------------------------------------------
__global__ void vq_prep(const float* __restrict__ cb) {
    int k = blockIdx.x * blockDim.x + threadIdx.x;
    if (k >= K_CODES) return;
    g_counts[k] = 0u;
    if (k == 0) g_sumsq = 0.0;
    const float4* cr = (const float4*)(cb + (size_t)k * D);
    uint2* oh = (uint2*)(g_eh + (size_t)k * D);
    uint2* ol = (uint2*)(g_el + (size_t)k * D);
    float s = 0.f;
#pragma unroll
    for (int i = 0; i < 16; ++i) {
        float4 v = cr[i];
        s = fmaf(v.x, v.x, s); s = fmaf(v.y, v.y, s);
        s = fmaf(v.z, v.z, s); s = fmaf(v.w, v.w, s);
        __nv_bfloat162 h01, h23, l01, l23;
        h01.x = __float2bfloat16(v.x); h01.y = __float2bfloat16(v.y);
        h23.x = __float2bfloat16(v.z); h23.y = __float2bfloat16(v.w);
        l01.x = __float2bfloat16(v.x - __bfloat162float(h01.x));
        l01.y = __float2bfloat16(v.y - __bfloat162float(h01.y));
        l23.x = __float2bfloat16(v.z - __bfloat162float(h23.x));
        l23.y = __float2bfloat16(v.w - __bfloat162float(h23.y));
        oh[i] = make_uint2(*(uint32_t*)&h01, *(uint32_t*)&h23);
        ol[i] = make_uint2(*(uint32_t*)&l01, *(uint32_t*)&l23);
    }
    g_esq[k] = s;
}

// ---------------------------------------------------------------------------
// stage a 128-code chunk of (eh, el) into smem with 16B-block XOR swizzle
// ---------------------------------------------------------------------------
__device__ __forceinline__ void stage_chunk(char* dst, int ch, int tid) {
    const uint4* sh = (const uint4*)((const char*)g_eh + (size_t)ch * 16384);
    const uint4* sl = (const uint4*)((const char*)g_el + (size_t)ch * 16384);
#pragma unroll
    for (int it = 0; it < 4; ++it) {
        int b = it * 256 + tid;
        int row = b >> 3, blk = b & 7;
        int off = row * 128 + ((blk ^ (row & 7)) << 4);
        *(uint4*)(dst + off) = sh[b];
        *(uint4*)(dst + 16384 + off) = sl[b];
    }
}

// ---------------------------------------------------------------------------
// Fused kernel: HMMA scan -> argmin (approx + exact rescue) -> full epilogue
//   CTA: 128 tokens, 256 thr (8 warps x 16 tokens); codes in 8 chunks of 128.
// ---------------------------------------------------------------------------
__global__ __launch_bounds__(256, 2) void vq_mma(const float* __restrict__ z,
                                                 const float* __restrict__ cb,
                                                 float* __restrict__ out, int N) {
    extern __shared__ __align__(1024) char smb[];
    const uint32_t sb = smem_u32(smb);
    float* zsq_s = (float*)(smb + OFF_ZSQ);
    float* esq_s = (float*)(smb + OFF_ESQ);
    int* widx_s = (int*)(smb + OFF_WIDX);
    float* bsum_s = (float*)(smb + OFF_BSUM);
    const int tid = threadIdx.x;
    const int w = tid >> 5, l = tid & 31;
    const int tok0 = blockIdx.x * 128;

    if (tid == 0) *bsum_s = 0.f;
    if (tid < 128) {   // zsq, sequential d ascending (matches R1)
        const float4* zr = (const float4*)(z + (size_t)(tok0 + tid) * D);
        float s = 0.f;
#pragma unroll
        for (int i = 0; i < 16; ++i) {
            float4 v = zr[i];
            s = fmaf(v.x, v.x, s); s = fmaf(v.y, v.y, s);
            s = fmaf(v.z, v.z, s); s = fmaf(v.w, v.w, s);
        }
        zsq_s[tid] = s;
    }
    for (int i = tid; i < K_CODES; i += 256) esq_s[i] = g_esq[i];

    // A fragments (zh, zl) straight from gmem
    const int r0 = w * 16 + (l >> 2), r1 = r0 + 8;
    uint32_t ah[4][4], al[4][4];
    {
        const float* zb = z + (size_t)tok0 * D;
#pragma unroll
        for (int ks = 0; ks < 4; ++ks) {
            int c = ks * 16 + (l & 3) * 2;
#pragma unroll
            for (int q = 0; q < 4; ++q) {
                int rr = (q & 1) ? r1 : r0;
                int cc = c + ((q >> 1) ? 8 : 0);
                float2 v = *(const float2*)(zb + (size_t)rr * D + cc);
                __nv_bfloat162 h, lo;
                h.x = __float2bfloat16(v.x); h.y = __float2bfloat16(v.y);
                lo.x = __float2bfloat16(v.x - __bfloat162float(h.x));
                lo.y = __float2bfloat16(v.y - __bfloat162float(h.y));
                ah[ks][q] = *(uint32_t*)&h;
                al[ks][q] = *(uint32_t*)&lo;
            }
        }
    }

    stage_chunk(smb + OFF_B0, 0, tid);
    __syncthreads();
    const float zs0 = zsq_s[w * 16 + (l >> 2)];
    const float zs1 = zsq_s[w * 16 + (l >> 2) + 8];

    float b1a = BIGF, b2a = BIGF, b1b = BIGF, b2b = BIGF;
    int i1a = 0x7FFFFFFF, i1b = 0x7FFFFFFF;

    const int g = l >> 3, ii = l & 7;
    for (int ch = 0; ch < 8; ++ch) {
        const int cur = ch & 1;
        if (ch < 7) stage_chunk(smb + (cur ? OFF_B0 : OFF_B1), ch + 1, tid);
        uint32_t bb = sb + (cur ? OFF_B1 : OFF_B0);
        uint32_t baseLo = bb + ii * 128 + ((g ^ ii) << 4);
        uint32_t baseHi = bb + ii * 128 + (((g + 4) ^ ii) << 4);
#pragma unroll 4
        for (int j = 0; j < 16; ++j) {
            uint32_t eh[8], el[8];
            ldsm4(eh, baseLo + j * 1024);
            ldsm4(eh + 4, baseHi + j * 1024);
            ldsm4(el, baseLo + 16384 + j * 1024);
            ldsm4(el + 4, baseHi + 16384 + j * 1024);
            float acc[4] = {0.f, 0.f, 0.f, 0.f};
#pragma unroll
            for (int ks = 0; ks < 4; ++ks) mma16816(acc, ah[ks], eh[2 * ks], eh[2 * ks + 1]);
#pragma unroll
            for (int ks = 0; ks < 4; ++ks) mma16816(acc, al[ks], eh[2 * ks], eh[2 * ks + 1]);
#pragma unroll
            for (int ks = 0; ks < 4; ++ks) mma16816(acc, ah[ks], el[2 * ks], el[2 * ks + 1]);

            int code0 = ch * 128 + j * 8 + (l & 3) * 2;
            float2 eq = *(const float2*)(esq_s + code0);
            track(b1a, i1a, b2a, (zs0 - 2.f * acc[0]) + eq.x, code0);
            track(b1a, i1a, b2a, (zs0 - 2.f * acc[1]) + eq.y, code0 + 1);
            track(b1b, i1b, b2b, (zs1 - 2.f * acc[2]) + eq.x, code0);
            track(b1b, i1b, b2b, (zs1 - 2.f * acc[3]) + eq.y, code0 + 1);
        }
        __syncthreads();
    }

    // quad reduce (lanes 4g..4g+3 hold rows r0, r1)
#pragma unroll
    for (int o = 1; o <= 2; o <<= 1) {
        float ob1 = __shfl_xor_sync(~0u, b1a, o);
        int oi1 = __shfl_xor_sync(~0u, i1a, o);
        float ob2 = __shfl_xor_sync(~0u, b2a, o);
        b2a = fminf(fminf(b2a, ob2), fmaxf(b1a, ob1));
        if (ob1 < b1a || (ob1 == b1a && oi1 < i1a)) { b1a = ob1; i1a = oi1; }
        ob1 = __shfl_xor_sync(~0u, b1b, o);
        oi1 = __shfl_xor_sync(~0u, i1b, o);
        ob2 = __shfl_xor_sync(~0u, b2b, o);
        b2b = fminf(fminf(b2b, ob2), fmaxf(b1b, ob1));
        if (ob1 < b1b || (ob1 == b1b && oi1 < i1b)) { b1b = ob1; i1b = oi1; }
    }
    if ((l & 3) == 0) {
        widx_s[r0] = i1a | ((b2a < b1a + WIN) ? 0x80000000 : 0);
        widx_s[r1] = i1b | ((b2b < b1b + WIN) ? 0x80000000 : 0);
    }
    __syncwarp();

    // exact rescue for ambiguous tokens (warp-cooperative, ascending code order)
    for (int t = 0; t < 16; ++t) {
        int lt = w * 16 + t;
        if (widx_s[lt] < 0) {
            const float* zr = z + (size_t)(tok0 + lt) * D;
            float zsq = zsq_s[lt];
            float s = BIGF;
            int bi = 0x7FFFFFFF;
            for (int c = l * 32; c < l * 32 + 32; ++c) {
                float sc = exact_score(zr, cb + (size_t)c * D, zsq, esq_s[c]);
                if (sc < s) { s = sc; bi = c; }
            }
#pragma unroll
            for (int o = 16; o > 0; o >>= 1) {
                float s2 = __shfl_xor_sync(~0u, s, o);
                int i2 = __shfl_xor_sync(~0u, bi, o);
                if (s2 < s || (s2 == s && i2 < bi)) { s = s2; bi = i2; }
            }
            if (l == 0) widx_s[lt] = bi;
        }
    }
    __syncthreads();

    // ---- epilogue: indices, histogram, z_q straight-through, sumsq ----
    if (tid < 128) {
        int bi = widx_s[tid] & 0x7FFFFFFF;
        out[(size_t)N * D + tok0 + tid] = (float)bi;
        atomicAdd(&g_counts[bi], 1u);
    }
    {
        int t = tid >> 1, half = tid & 1;
        int bi = widx_s[t] & 0x7FFFFFFF;
        const float4* cr = (const float4*)(cb + (size_t)bi * D + half * 32);
        const float4* zr = (const float4*)(z + (size_t)(tok0 + t) * D + half * 32);
        float4* orow = (float4*)(out + (size_t)(tok0 + t) * D + half * 32);
        float part = 0.f;
#pragma unroll
        for (int i = 0; i < 8; ++i) {
            float4 cv = cr[i], zv = zr[i];
            float dx = cv.x - zv.x, dy = cv.y - zv.y;
            float dz = cv.z - zv.z, dw = cv.w - zv.w;
            orow[i] = make_float4(zv.x + dx, zv.y + dy, zv.z + dz, zv.w + dw);
            part += dx * dx + dy * dy + dz * dz + dw * dw;
        }
#pragma unroll
        for (int o = 16; o > 0; o >>= 1) part += __shfl_xor_sync(~0u, part, o);
        if (l == 0) atomicAdd(bsum_s, part);
    }
    __syncthreads();
    if (tid == 0) atomicAdd(&g_sumsq, (double)*bsum_s);
}

// ---------------------------------------------------------------------------
// Finalize: entropy / perplexity / losses (fp32, like the reference)
// ---------------------------------------------------------------------------
__global__ void vq_finalize(float* __restrict__ out, int N) {
    int k = threadIdx.x, lane = k & 31, w = k >> 5;
    float avg = (float)g_counts[k] / (float)N + 1e-10f;
    float term = -avg * logf(avg);
#pragma unroll
    for (int o = 16; o > 0; o >>= 1) term += __shfl_xor_sync(~0u, term, o);
    __shared__ float ws[32];
    if (lane == 0) ws[w] = term;
    __syncthreads();
    if (w == 0) {
        float v = ws[lane];
#pragma unroll
        for (int o = 16; o > 0; o >>= 1) v += __shfl_xor_sync(~0u, v, o);
        if (lane == 0) {
            float H = v;
            double mean = g_sumsq / ((double)N * D);
            size_t base = (size_t)N * D + N;
            out[base + 0] = (float)mean;
            out[base + 1] = (float)(0.25 * mean);
            out[base + 2] = -0.1f * (H / logf(1024.0f));
            out[base + 3] = expf(H);
        }
    }
}

// ---------------------------------------------------------------------------
extern "C" void kernel_launch(void* const* d_in, const int* in_sizes, int n_in,
                              void* d_out, int out_size) {
    const float* z = (const float*)d_in[0];
    const float* cb = (const float*)d_in[1];
    float* out = (float*)d_out;
    int N = in_sizes[0] / D;

    cudaFuncSetAttribute(vq_mma, cudaFuncAttributeMaxDynamicSharedMemorySize, SMEM_SZ);

    vq_prep<<<8, 128>>>(cb);
    vq_mma<<<N / 128, 256, SMEM_SZ>>>(z, cb, out, N);
    vq_finalize<<<1, 1024>>>(out, N);
}